// round 16
// baseline (speedup 1.0000x reference)
#include <cuda_runtime.h>
#include <cuda_bf16.h>
#include <cuda_fp16.h>
#include <math.h>

#define NN 100000
#define NE 1600000
#define NG 100
#define NH 8
#define NC 16
#define NF 128

// ---------------- scratch (static device globals) ---------------------------
__device__ __align__(16) __nv_bfloat16 g_hb[(size_t)NN * NF];  // 25.6 MB h (bf16)
__device__ __align__(16) __half g_w[(size_t)NE * NH];          // 25.6 MB edge weights
__device__ __align__(16) float g_asrc[NN * NH];
__device__ __align__(16) float g_adst[NN * NH];
__device__ __align__(16) float g_s[NN * NH];           // denom, then 0.125/s
__device__ __align__(16) float g_acc[NN * NC];         // head-averaged message accum
__device__ __align__(16) float g_colsum[NF];
__device__ __align__(16) float g_colsq[NF];
__device__ __align__(16) float g_WpT[NF * NF];         // BN-folded weights, [n][k]
__device__ __align__(16) float g_bp[NF];               // BN-folded bias
__device__ __align__(16) float g_pool[NG * NC];
__device__ __align__(16) float g_cnt[NG];

// vector reduction (no return) ----------------------------------------------
__device__ __forceinline__ void red_v4(float* p, float a, float b, float c, float d) {
    asm volatile("red.global.add.v4.f32 [%0], {%1, %2, %3, %4};"
                 :: "l"(p), "f"(a), "f"(b), "f"(c), "f"(d) : "memory");
}

__device__ __forceinline__ unsigned f2tf32(float f) {
    unsigned r;
    asm("cvt.rna.tf32.f32 %0, %1;" : "=r"(r) : "f"(f));
    return r;
}

__device__ __forceinline__ void bn_coeff(int k, const float* gamma, const float* beta,
                                         float& sc, float& sh) {
    float mean = g_colsum[k] * (1.f / NN);
    float var = g_colsq[k] * (1.f / NN) - mean * mean;
    sc = gamma[k] * rsqrtf(var + 1e-5f);
    sh = beta[k] - mean * sc;
}

// ---------------- K0b: zero colsum/colsq ------------------------------------
__global__ void k_zero_stats() {
    int i = threadIdx.x;
    if (i < NF) { g_colsum[i] = 0.f; g_colsq[i] = 0.f; }
}

// ---------------- K1: BN column stats + zero accumulators -------------------
__global__ void k_stats(const float* __restrict__ x) {
    __shared__ float ssum[NF];
    __shared__ float ssq[NF];
    int t = threadIdx.x;
    int lane = t & 31;
    int warp = t >> 5;
    int col = lane * 4;
    if (t < NF) { ssum[t] = 0.f; ssq[t] = 0.f; }
    __syncthreads();

    int gi = blockIdx.x * blockDim.x + t;
    int gst = gridDim.x * blockDim.x;
    for (int k = gi; k < NN * NC; k += gst) g_acc[k] = 0.f;
    if (gi < NG * NC) g_pool[gi] = 0.f;
    if (gi < NG) g_cnt[gi] = 0.f;

    float s0 = 0.f, s1 = 0.f, s2 = 0.f, s3 = 0.f;
    float q0 = 0.f, q1 = 0.f, q2 = 0.f, q3 = 0.f;
    int row = blockIdx.x * 8 + warp;
    int step = gridDim.x * 8;
    for (int r = row; r < NN; r += step) {
        float4 v = *(const float4*)(x + (size_t)r * NF + col);
        s0 += v.x; s1 += v.y; s2 += v.z; s3 += v.w;
        q0 += v.x * v.x; q1 += v.y * v.y; q2 += v.z * v.z; q3 += v.w * v.w;
    }
    atomicAdd(&ssum[col + 0], s0); atomicAdd(&ssum[col + 1], s1);
    atomicAdd(&ssum[col + 2], s2); atomicAdd(&ssum[col + 3], s3);
    atomicAdd(&ssq[col + 0], q0);  atomicAdd(&ssq[col + 1], q1);
    atomicAdd(&ssq[col + 2], q2);  atomicAdd(&ssq[col + 3], q3);
    __syncthreads();
    if (t < NF) {
        atomicAdd(&g_colsum[t], ssum[t]);
        atomicAdd(&g_colsq[t], ssq[t]);
    }
}

// ---------------- K2b: fold BN into weights; store TRANSPOSED [n][k] --------
__global__ void k_prep(const float* __restrict__ W,
                       const float* __restrict__ gamma,
                       const float* __restrict__ beta) {
    if (blockIdx.x < 16) {
        __shared__ float sm[32][33];
        int kt = (blockIdx.x >> 2) * 32;
        int jt = (blockIdx.x & 3) * 32;
        int r = threadIdx.x >> 3;
        int c4 = (threadIdx.x & 7) * 4;
        float sc, sh;
        bn_coeff(kt + r, gamma, beta, sc, sh);
        float4 v = *(const float4*)(W + (size_t)(kt + r) * NF + jt + c4);
        sm[c4 + 0][r] = sc * v.x;
        sm[c4 + 1][r] = sc * v.y;
        sm[c4 + 2][r] = sc * v.z;
        sm[c4 + 3][r] = sc * v.w;
        __syncthreads();
        float4 o = make_float4(sm[r][c4], sm[r][c4 + 1], sm[r][c4 + 2], sm[r][c4 + 3]);
        *(float4*)(g_WpT + (size_t)(jt + r) * NF + kt + c4) = o;
    } else {
        __shared__ float ssh[NF];
        if (threadIdx.x < NF) {
            float sc, sh;
            bn_coeff(threadIdx.x, gamma, beta, sc, sh);
            ssh[threadIdx.x] = sh;
        }
        __syncthreads();
        int j = (blockIdx.x - 16) * 8 + (threadIdx.x >> 5);
        int lane = threadIdx.x & 31;
        float b = 0.f;
#pragma unroll
        for (int k = lane; k < NF; k += 32)
            b = fmaf(ssh[k], W[k * NF + j], b);
        b += __shfl_xor_sync(0xffffffffu, b, 16);
        b += __shfl_xor_sync(0xffffffffu, b, 8);
        b += __shfl_xor_sync(0xffffffffu, b, 4);
        b += __shfl_xor_sync(0xffffffffu, b, 2);
        b += __shfl_xor_sync(0xffffffffu, b, 1);
        if (lane == 0) g_bp[j] = b;
    }
}

// ---------------- K3: tensor-core GEMM x@W' + b' + logits -------------------
#define XS_STRIDE 40
#define WS_STRIDE 136
#define XCHUNK_FLOATS (128 * XS_STRIDE)
#define WSM_FLOATS (NF * WS_STRIDE)
#define GEMM_SMEM_BYTES ((WSM_FLOATS + 2 * XCHUNK_FLOATS) * 4)

#define MMA_TF32(d, a, b)                                                     \
    asm volatile(                                                             \
        "mma.sync.aligned.m16n8k8.row.col.f32.tf32.tf32.f32 "                 \
        "{%0,%1,%2,%3}, {%4,%5,%6,%7}, {%8,%9}, {%0,%1,%2,%3};"               \
        : "+f"(d[0]), "+f"(d[1]), "+f"(d[2]), "+f"(d[3])                      \
        : "r"(a[0]), "r"(a[1]), "r"(a[2]), "r"(a[3]), "r"(b[0]), "r"(b[1]))

__device__ __forceinline__ void cp16(void* dst_smem, const void* src, int sz) {
    unsigned d = (unsigned)__cvta_generic_to_shared(dst_smem);
    asm volatile("cp.async.cg.shared.global [%0], [%1], 16, %2;"
                 :: "r"(d), "l"(src), "r"(sz));
}
#define CP_COMMIT() asm volatile("cp.async.commit_group;")

__global__ void __launch_bounds__(256, 2)
k_gemm(const float* __restrict__ x,
       const float* __restrict__ attS, const float* __restrict__ attD) {
    extern __shared__ float smem[];
    float* Wsm = smem;                       // [n][k] stride 136 (tf32 bits)
    float* Xs0 = smem + WSM_FLOATS;          // [row][k] stride 40 (raw fp32)
    float* Xs1 = Xs0 + XCHUNK_FLOATS;

    int t = threadIdx.x;
    int lane = t & 31;
    int wid = t >> 5;
    int g = lane >> 2, tg = lane & 3;
    int wm = wid & 1, wn = wid >> 1;
    int r0 = blockIdx.x * 128;

#pragma unroll
    for (int p = 0; p < 4; ++p) {
        int idx = t + p * 256;
        int row = idx >> 3, grp = idx & 7;
        int n = r0 + row;
        cp16(Xs0 + row * XS_STRIDE + grp * 4,
             x + (size_t)n * NF + grp * 4, (n < NN) ? 16 : 0);
    }
    CP_COMMIT();

#pragma unroll
    for (int p = 0; p < 16; ++p) {
        int i = t + p * 256;
        int row = i >> 5, grp = i & 31;
        float4 v = ((const float4*)(g_WpT + row * NF))[grp];
        unsigned* dst = (unsigned*)(Wsm + row * WS_STRIDE + grp * 4);
        dst[0] = f2tf32(v.x); dst[1] = f2tf32(v.y);
        dst[2] = f2tf32(v.z); dst[3] = f2tf32(v.w);
    }

    float acc[4][4][4];
#pragma unroll
    for (int i = 0; i < 4; ++i)
#pragma unroll
        for (int j = 0; j < 4; ++j)
#pragma unroll
            for (int c = 0; c < 4; ++c) acc[i][j][c] = 0.f;

#pragma unroll
    for (int kc = 0; kc < 4; ++kc) {
        if (kc < 3) {
            float* Xs = (kc & 1) ? Xs0 : Xs1;
            int kbase = (kc + 1) * 32;
#pragma unroll
            for (int p = 0; p < 4; ++p) {
                int idx = t + p * 256;
                int row = idx >> 3, grp = idx & 7;
                int n = r0 + row;
                cp16(Xs + row * XS_STRIDE + grp * 4,
                     x + (size_t)n * NF + kbase + grp * 4, (n < NN) ? 16 : 0);
            }
            CP_COMMIT();
            asm volatile("cp.async.wait_group 1;");
        } else {
            asm volatile("cp.async.wait_group 0;");
        }
        __syncthreads();

        const float* Xs = (kc & 1) ? Xs1 : Xs0;
#pragma unroll
        for (int ks = 0; ks < 4; ++ks) {
            int k = ks * 8;
            unsigned a[4][4], b[4][2];
#pragma unroll
            for (int i = 0; i < 4; ++i) {
                int rlo = wm * 64 + i * 16 + g;
                float2 Alo = *(const float2*)(Xs + rlo * XS_STRIDE + k + 2 * tg);
                float2 Ahi = *(const float2*)(Xs + (rlo + 8) * XS_STRIDE + k + 2 * tg);
                a[i][0] = f2tf32(Alo.x);
                a[i][1] = f2tf32(Ahi.x);
                a[i][2] = f2tf32(Alo.y);
                a[i][3] = f2tf32(Ahi.y);
            }
#pragma unroll
            for (int j = 0; j < 4; ++j) {
                int c = wn * 32 + j * 8 + g;
                float2 B = *(const float2*)(Wsm + c * WS_STRIDE + kc * 32 + k + 2 * tg);
                b[j][0] = __float_as_uint(B.x);
                b[j][1] = __float_as_uint(B.y);
            }
#pragma unroll
            for (int i = 0; i < 4; ++i)
#pragma unroll
                for (int j = 0; j < 4; ++j) MMA_TF32(acc[i][j], a[i], b[j]);
        }
        __syncthreads();
    }

    int rowsValid = NN - r0;
    if (rowsValid > 128) rowsValid = 128;

#pragma unroll
    for (int j = 0; j < 4; ++j) {
        int c0 = wn * 32 + j * 8 + 2 * tg;
        float b0 = g_bp[c0], b1 = g_bp[c0 + 1];
#pragma unroll
        for (int i = 0; i < 4; ++i) {
            acc[i][j][0] += b0; acc[i][j][1] += b1;
            acc[i][j][2] += b0; acc[i][j][3] += b1;
        }
    }

#pragma unroll
    for (int i = 0; i < 4; ++i) {
        int rlo = wm * 64 + i * 16 + g;
        int rhi = rlo + 8;
#pragma unroll
        for (int j = 0; j < 4; ++j) {
            int c0 = wn * 32 + j * 8 + 2 * tg;
            if (rlo < rowsValid) {
                __nv_bfloat162 p = __float22bfloat162_rn(
                    make_float2(acc[i][j][0], acc[i][j][1]));
                *(__nv_bfloat162*)(g_hb + (size_t)(r0 + rlo) * NF + c0) = p;
            }
            if (rhi < rowsValid) {
                __nv_bfloat162 p = __float22bfloat162_rn(
                    make_float2(acc[i][j][2], acc[i][j][3]));
                *(__nv_bfloat162*)(g_hb + (size_t)(r0 + rhi) * NF + c0) = p;
            }
        }
    }

    float aS[2][2][2], aD[2][2][2];
#pragma unroll
    for (int hl = 0; hl < 2; ++hl)
#pragma unroll
        for (int j2 = 0; j2 < 2; ++j2) {
            int base = (2 * wn + hl) * 16 + j2 * 8 + 2 * tg;
            aS[hl][j2][0] = attS[base];     aS[hl][j2][1] = attS[base + 1];
            aD[hl][j2][0] = attD[base];     aD[hl][j2][1] = attD[base + 1];
        }

#pragma unroll
    for (int i = 0; i < 4; ++i) {
#pragma unroll
        for (int hl = 0; hl < 2; ++hl) {
            float psl = 0.f, pdl = 0.f, psh = 0.f, pdh = 0.f;
#pragma unroll
            for (int j2 = 0; j2 < 2; ++j2) {
                int j = 2 * hl + j2;
                psl = fmaf(acc[i][j][0], aS[hl][j2][0],
                      fmaf(acc[i][j][1], aS[hl][j2][1], psl));
                pdl = fmaf(acc[i][j][0], aD[hl][j2][0],
                      fmaf(acc[i][j][1], aD[hl][j2][1], pdl));
                psh = fmaf(acc[i][j][2], aS[hl][j2][0],
                      fmaf(acc[i][j][3], aS[hl][j2][1], psh));
                pdh = fmaf(acc[i][j][2], aD[hl][j2][0],
                      fmaf(acc[i][j][3], aD[hl][j2][1], pdh));
            }
            psl += __shfl_xor_sync(0xffffffffu, psl, 1);
            psl += __shfl_xor_sync(0xffffffffu, psl, 2);
            pdl += __shfl_xor_sync(0xffffffffu, pdl, 1);
            pdl += __shfl_xor_sync(0xffffffffu, pdl, 2);
            psh += __shfl_xor_sync(0xffffffffu, psh, 1);
            psh += __shfl_xor_sync(0xffffffffu, psh, 2);
            pdh += __shfl_xor_sync(0xffffffffu, pdh, 1);
            pdh += __shfl_xor_sync(0xffffffffu, pdh, 2);
            if (tg == 0) {
                int h = 2 * wn + hl;
                int rlo = wm * 64 + i * 16 + g;
                int rhi = rlo + 8;
                if (rlo < rowsValid) {
                    int n = r0 + rlo;
                    g_asrc[n * NH + h] = psl;
                    g_adst[n * NH + h] = pdl;
                    float e = psl + pdl;
                    e = e > 0.f ? e : 0.2f * e;
                    g_s[n * NH + h] = __expf(e);
                }
                if (rhi < rowsValid) {
                    int n = r0 + rhi;
                    g_asrc[n * NH + h] = psh;
                    g_adst[n * NH + h] = pdh;
                    float e = psh + pdh;
                    e = e > 0.f ? e : 0.2f * e;
                    g_s[n * NH + h] = __expf(e);
                }
            }
        }
    }
}

// ---------------- K4: edge pass 1 — weights + denominators -----------------
__device__ __forceinline__ float lrelu_exp(float a, float b) {
    float e = a + b;
    e = e > 0.f ? e : 0.2f * e;
    return __expf(e);
}

__global__ void k_edge_s(const int* __restrict__ ei) {
    int e = blockIdx.x * blockDim.x + threadIdx.x;
    if (e >= NE) return;
    int s = ei[e];
    int d = ei[NE + e];
    float4 a0 = *(const float4*)(g_asrc + s * NH);
    float4 a1 = *(const float4*)(g_asrc + s * NH + 4);
    float4 b0 = *(const float4*)(g_adst + d * NH);
    float4 b1 = *(const float4*)(g_adst + d * NH + 4);
    float w0 = lrelu_exp(a0.x, b0.x), w1 = lrelu_exp(a0.y, b0.y);
    float w2 = lrelu_exp(a0.z, b0.z), w3 = lrelu_exp(a0.w, b0.w);
    float w4 = lrelu_exp(a1.x, b1.x), w5 = lrelu_exp(a1.y, b1.y);
    float w6 = lrelu_exp(a1.z, b1.z), w7 = lrelu_exp(a1.w, b1.w);
    __half2 hw[4];
    hw[0] = __floats2half2_rn(w0, w1);
    hw[1] = __floats2half2_rn(w2, w3);
    hw[2] = __floats2half2_rn(w4, w5);
    hw[3] = __floats2half2_rn(w6, w7);
    *(uint4*)(g_w + (size_t)e * NH) = *(uint4*)hw;
    float* sp = g_s + d * NH;
    red_v4(sp, w0, w1, w2, w3);
    red_v4(sp + 4, w4, w5, w6, w7);
}

// ---------------- K4b: g_s <- 0.125 / s ------------------------------------
__global__ void k_sinv() {
    int i = blockIdx.x * blockDim.x + threadIdx.x;
    if (i < NN * NH) g_s[i] = 0.125f * __frcp_rn(g_s[i]);
}

// ---------------- K5: edge pass 2 — message scatter (4 threads/edge) -------
// h gathered as 8 x LDG.64 (batched upfront for MLP), alphas via shfl.
__global__ void k_edge_msg(const int* __restrict__ ei) {
    int gt = blockIdx.x * blockDim.x + threadIdx.x;
    int e = gt >> 2, q = gt & 3;
    if (e >= NE) return;
    int s = ei[e];
    int d = ei[NE + e];

    // batch all h loads up front (8 x 8B, independent -> full MLP)
    const __nv_bfloat16* hrow = g_hb + (size_t)s * NF + q * 4;
    uint2 hu[NH];
#pragma unroll
    for (int h = 0; h < NH; ++h)
        hu[h] = *(const uint2*)(hrow + h * 16);

    __half2 w2 = *(const __half2*)(g_w + (size_t)e * NH + q * 2);
    float2 wf = __half22float2(w2);
    float2 si2 = *(const float2*)(g_s + d * NH + q * 2);  // 0.125/s
    float2 alq;
    alq.x = wf.x * si2.x;
    alq.y = wf.y * si2.y;

    unsigned long long v0 = *(unsigned long long*)&alq;
    unsigned long long v1 = __shfl_xor_sync(0xffffffffu, v0, 1);
    unsigned long long v2 = __shfl_xor_sync(0xffffffffu, v0, 2);
    unsigned long long v3 = __shfl_xor_sync(0xffffffffu, v1, 2);
    float2 p1 = *(float2*)&v1, p2 = *(float2*)&v2, p3 = *(float2*)&v3;

    float al[8];
#pragma unroll
    for (int i = 0; i < 4; ++i) {
        int r = i ^ q;
        float2 p = (r == 0) ? alq : (r == 1) ? p1 : (r == 2) ? p2 : p3;
        al[2 * i] = p.x;
        al[2 * i + 1] = p.y;
    }

    float r0 = 0.f, r1 = 0.f, r2 = 0.f, r3 = 0.f;
#pragma unroll
    for (int h = 0; h < NH; ++h) {
        __nv_bfloat162 p01 = *(__nv_bfloat162*)&hu[h].x;
        __nv_bfloat162 p23 = *(__nv_bfloat162*)&hu[h].y;
        float2 f01 = __bfloat1622float2(p01);
        float2 f23 = __bfloat1622float2(p23);
        r0 = fmaf(al[h], f01.x, r0);
        r1 = fmaf(al[h], f01.y, r1);
        r2 = fmaf(al[h], f23.x, r2);
        r3 = fmaf(al[h], f23.y, r3);
    }
    red_v4(g_acc + d * NC + q * 4, r0, r1, r2, r3);
}

// ---------------- K6: node finalize (self-loop + bias + ELU + pool) --------
__global__ void k_node_final(const int* __restrict__ batch,
                             const float* __restrict__ bias) {
    int gt = blockIdx.x * blockDim.x + threadIdx.x;
    int n = gt >> 4, c = gt & 15;
    if (n >= NN) return;
    float v = g_acc[n * NC + c];
    const __nv_bfloat16* hr = g_hb + (size_t)n * NF;
#pragma unroll
    for (int h = 0; h < NH; ++h) {
        float a = g_asrc[n * NH + h] + g_adst[n * NH + h];
        a = a > 0.f ? a : 0.2f * a;
        float w = __expf(a) * g_s[n * NH + h];   // g_s holds 0.125/s
        v = fmaf(w, __bfloat162float(hr[h * 16 + c]), v);
    }
    v += bias[c];
    v = v > 0.f ? v : expm1f(v);
    int b = batch[n];
    atomicAdd(&g_pool[b * NC + c], v);
    if (c == 0) atomicAdd(&g_cnt[b], 1.0f);
}

// ---------------- K7: pooled mean ------------------------------------------
__global__ void k_pool_div(float* __restrict__ out) {
    int i = blockIdx.x * blockDim.x + threadIdx.x;
    if (i < NG * NC) {
        int g = i >> 4;
        out[i] = g_pool[i] / fmaxf(g_cnt[g], 1.0f);
    }
}

// ---------------- launch ----------------------------------------------------
extern "C" void kernel_launch(void* const* d_in, const int* in_sizes, int n_in,
                              void* d_out, int out_size) {
    const float* x = (const float*)d_in[0];
    const int* ei = (const int*)d_in[1];
    const int* batch = (const int*)d_in[2];
    const float* gamma = (const float*)d_in[3];
    const float* beta = (const float*)d_in[4];
    const float* W = (const float*)d_in[5];
    const float* attS = (const float*)d_in[6];
    const float* attD = (const float*)d_in[7];
    const float* bias = (const float*)d_in[8];
    float* out = (float*)d_out;

    cudaFuncSetAttribute(k_gemm, cudaFuncAttributeMaxDynamicSharedMemorySize,
                         GEMM_SMEM_BYTES);

    k_zero_stats<<<1, 128>>>();
    k_stats<<<512, 256>>>(x);
    k_prep<<<32, 256>>>(W, gamma, beta);
    k_gemm<<<(NN + 127) / 128, 256, GEMM_SMEM_BYTES>>>(x, attS, attD);
    k_edge_s<<<(NE + 255) / 256, 256>>>(ei);
    k_sinv<<<(NN * NH + 255) / 256, 256>>>();
    k_edge_msg<<<(NE * 4 + 255) / 256, 256>>>(ei);
    k_node_final<<<(NN * 16 + 255) / 256, 256>>>(batch, bias);
    k_pool_div<<<(NG * NC + 255) / 256, 256>>>(out);
}

// round 17
// speedup vs baseline: 1.0157x; 1.0157x over previous
#include <cuda_runtime.h>
#include <cuda_bf16.h>
#include <cuda_fp16.h>
#include <math.h>

#define NN 100000
#define NE 1600000
#define NG 100
#define NH 8
#define NC 16
#define NF 128

// ---------------- scratch (static device globals) ---------------------------
__device__ __align__(16) __nv_bfloat16 g_hb[(size_t)NN * NF];  // 25.6 MB h (bf16)
__device__ __align__(16) __half g_w[(size_t)NE * NH];          // 25.6 MB edge weights
__device__ __align__(16) float g_asrc[NN * NH];
__device__ __align__(16) float g_adst[NN * NH];
__device__ __align__(16) float g_s[NN * NH];           // denom, then 0.125/s
__device__ __align__(16) float g_wself[NN * NH];       // self-loop alpha/8
__device__ __align__(16) float g_acc[NN * NC];         // head-averaged message accum
__device__ __align__(16) float g_colsum[NF];
__device__ __align__(16) float g_colsq[NF];
__device__ __align__(16) float g_WpT[NF * NF];         // BN-folded weights, [n][k]
__device__ __align__(16) float g_bp[NF];               // BN-folded bias
__device__ __align__(16) float g_pool[NG * NC];
__device__ __align__(16) float g_cnt[NG];

// vector reduction (no return) ----------------------------------------------
__device__ __forceinline__ void red_v4(float* p, float a, float b, float c, float d) {
    asm volatile("red.global.add.v4.f32 [%0], {%1, %2, %3, %4};"
                 :: "l"(p), "f"(a), "f"(b), "f"(c), "f"(d) : "memory");
}

__device__ __forceinline__ unsigned f2tf32(float f) {
    unsigned r;
    asm("cvt.rna.tf32.f32 %0, %1;" : "=r"(r) : "f"(f));
    return r;
}

__device__ __forceinline__ void bn_coeff(int k, const float* gamma, const float* beta,
                                         float& sc, float& sh) {
    float mean = g_colsum[k] * (1.f / NN);
    float var = g_colsq[k] * (1.f / NN) - mean * mean;
    sc = gamma[k] * rsqrtf(var + 1e-5f);
    sh = beta[k] - mean * sc;
}

// ---------------- K0b: zero colsum/colsq ------------------------------------
__global__ void k_zero_stats() {
    int i = threadIdx.x;
    if (i < NF) { g_colsum[i] = 0.f; g_colsq[i] = 0.f; }
}

// ---------------- K1: BN column stats + zero accumulators -------------------
__global__ void k_stats(const float* __restrict__ x) {
    __shared__ float ssum[NF];
    __shared__ float ssq[NF];
    int t = threadIdx.x;
    int lane = t & 31;
    int warp = t >> 5;
    int col = lane * 4;
    if (t < NF) { ssum[t] = 0.f; ssq[t] = 0.f; }
    __syncthreads();

    int gi = blockIdx.x * blockDim.x + t;
    int gst = gridDim.x * blockDim.x;
    for (int k = gi; k < NN * NC; k += gst) g_acc[k] = 0.f;
    if (gi < NG * NC) g_pool[gi] = 0.f;
    if (gi < NG) g_cnt[gi] = 0.f;

    float s0 = 0.f, s1 = 0.f, s2 = 0.f, s3 = 0.f;
    float q0 = 0.f, q1 = 0.f, q2 = 0.f, q3 = 0.f;
    int row = blockIdx.x * 8 + warp;
    int step = gridDim.x * 8;
    for (int r = row; r < NN; r += step) {
        float4 v = *(const float4*)(x + (size_t)r * NF + col);
        s0 += v.x; s1 += v.y; s2 += v.z; s3 += v.w;
        q0 += v.x * v.x; q1 += v.y * v.y; q2 += v.z * v.z; q3 += v.w * v.w;
    }
    atomicAdd(&ssum[col + 0], s0); atomicAdd(&ssum[col + 1], s1);
    atomicAdd(&ssum[col + 2], s2); atomicAdd(&ssum[col + 3], s3);
    atomicAdd(&ssq[col + 0], q0);  atomicAdd(&ssq[col + 1], q1);
    atomicAdd(&ssq[col + 2], q2);  atomicAdd(&ssq[col + 3], q3);
    __syncthreads();
    if (t < NF) {
        atomicAdd(&g_colsum[t], ssum[t]);
        atomicAdd(&g_colsq[t], ssq[t]);
    }
}

// ---------------- K2b: fold BN into weights; store TRANSPOSED [n][k] --------
__global__ void k_prep(const float* __restrict__ W,
                       const float* __restrict__ gamma,
                       const float* __restrict__ beta) {
    if (blockIdx.x < 16) {
        __shared__ float sm[32][33];
        int kt = (blockIdx.x >> 2) * 32;
        int jt = (blockIdx.x & 3) * 32;
        int r = threadIdx.x >> 3;
        int c4 = (threadIdx.x & 7) * 4;
        float sc, sh;
        bn_coeff(kt + r, gamma, beta, sc, sh);
        float4 v = *(const float4*)(W + (size_t)(kt + r) * NF + jt + c4);
        sm[c4 + 0][r] = sc * v.x;
        sm[c4 + 1][r] = sc * v.y;
        sm[c4 + 2][r] = sc * v.z;
        sm[c4 + 3][r] = sc * v.w;
        __syncthreads();
        float4 o = make_float4(sm[r][c4], sm[r][c4 + 1], sm[r][c4 + 2], sm[r][c4 + 3]);
        *(float4*)(g_WpT + (size_t)(jt + r) * NF + kt + c4) = o;
    } else {
        __shared__ float ssh[NF];
        if (threadIdx.x < NF) {
            float sc, sh;
            bn_coeff(threadIdx.x, gamma, beta, sc, sh);
            ssh[threadIdx.x] = sh;
        }
        __syncthreads();
        int j = (blockIdx.x - 16) * 8 + (threadIdx.x >> 5);
        int lane = threadIdx.x & 31;
        float b = 0.f;
#pragma unroll
        for (int k = lane; k < NF; k += 32)
            b = fmaf(ssh[k], W[k * NF + j], b);
        b += __shfl_xor_sync(0xffffffffu, b, 16);
        b += __shfl_xor_sync(0xffffffffu, b, 8);
        b += __shfl_xor_sync(0xffffffffu, b, 4);
        b += __shfl_xor_sync(0xffffffffu, b, 2);
        b += __shfl_xor_sync(0xffffffffu, b, 1);
        if (lane == 0) g_bp[j] = b;
    }
}

// ---------------- K3: tensor-core GEMM x@W' + b' + logits -------------------
#define XS_STRIDE 40
#define WS_STRIDE 136
#define XCHUNK_FLOATS (128 * XS_STRIDE)
#define WSM_FLOATS (NF * WS_STRIDE)
#define GEMM_SMEM_BYTES ((WSM_FLOATS + 2 * XCHUNK_FLOATS) * 4)

#define MMA_TF32(d, a, b)                                                     \
    asm volatile(                                                             \
        "mma.sync.aligned.m16n8k8.row.col.f32.tf32.tf32.f32 "                 \
        "{%0,%1,%2,%3}, {%4,%5,%6,%7}, {%8,%9}, {%0,%1,%2,%3};"               \
        : "+f"(d[0]), "+f"(d[1]), "+f"(d[2]), "+f"(d[3])                      \
        : "r"(a[0]), "r"(a[1]), "r"(a[2]), "r"(a[3]), "r"(b[0]), "r"(b[1]))

__device__ __forceinline__ void cp16(void* dst_smem, const void* src, int sz) {
    unsigned d = (unsigned)__cvta_generic_to_shared(dst_smem);
    asm volatile("cp.async.cg.shared.global [%0], [%1], 16, %2;"
                 :: "r"(d), "l"(src), "r"(sz));
}
#define CP_COMMIT() asm volatile("cp.async.commit_group;")

__global__ void __launch_bounds__(256, 2)
k_gemm(const float* __restrict__ x,
       const float* __restrict__ attS, const float* __restrict__ attD) {
    extern __shared__ float smem[];
    float* Wsm = smem;                       // [n][k] stride 136 (tf32 bits)
    float* Xs0 = smem + WSM_FLOATS;          // [row][k] stride 40 (raw fp32)
    float* Xs1 = Xs0 + XCHUNK_FLOATS;

    int t = threadIdx.x;
    int lane = t & 31;
    int wid = t >> 5;
    int g = lane >> 2, tg = lane & 3;
    int wm = wid & 1, wn = wid >> 1;
    int r0 = blockIdx.x * 128;

#pragma unroll
    for (int p = 0; p < 4; ++p) {
        int idx = t + p * 256;
        int row = idx >> 3, grp = idx & 7;
        int n = r0 + row;
        cp16(Xs0 + row * XS_STRIDE + grp * 4,
             x + (size_t)n * NF + grp * 4, (n < NN) ? 16 : 0);
    }
    CP_COMMIT();

#pragma unroll
    for (int p = 0; p < 16; ++p) {
        int i = t + p * 256;
        int row = i >> 5, grp = i & 31;
        float4 v = ((const float4*)(g_WpT + row * NF))[grp];
        unsigned* dst = (unsigned*)(Wsm + row * WS_STRIDE + grp * 4);
        dst[0] = f2tf32(v.x); dst[1] = f2tf32(v.y);
        dst[2] = f2tf32(v.z); dst[3] = f2tf32(v.w);
    }

    float acc[4][4][4];
#pragma unroll
    for (int i = 0; i < 4; ++i)
#pragma unroll
        for (int j = 0; j < 4; ++j)
#pragma unroll
            for (int c = 0; c < 4; ++c) acc[i][j][c] = 0.f;

#pragma unroll
    for (int kc = 0; kc < 4; ++kc) {
        if (kc < 3) {
            float* Xs = (kc & 1) ? Xs0 : Xs1;
            int kbase = (kc + 1) * 32;
#pragma unroll
            for (int p = 0; p < 4; ++p) {
                int idx = t + p * 256;
                int row = idx >> 3, grp = idx & 7;
                int n = r0 + row;
                cp16(Xs + row * XS_STRIDE + grp * 4,
                     x + (size_t)n * NF + kbase + grp * 4, (n < NN) ? 16 : 0);
            }
            CP_COMMIT();
            asm volatile("cp.async.wait_group 1;");
        } else {
            asm volatile("cp.async.wait_group 0;");
        }
        __syncthreads();

        const float* Xs = (kc & 1) ? Xs1 : Xs0;
#pragma unroll
        for (int ks = 0; ks < 4; ++ks) {
            int k = ks * 8;
            unsigned a[4][4], b[4][2];
#pragma unroll
            for (int i = 0; i < 4; ++i) {
                int rlo = wm * 64 + i * 16 + g;
                float2 Alo = *(const float2*)(Xs + rlo * XS_STRIDE + k + 2 * tg);
                float2 Ahi = *(const float2*)(Xs + (rlo + 8) * XS_STRIDE + k + 2 * tg);
                a[i][0] = f2tf32(Alo.x);
                a[i][1] = f2tf32(Ahi.x);
                a[i][2] = f2tf32(Alo.y);
                a[i][3] = f2tf32(Ahi.y);
            }
#pragma unroll
            for (int j = 0; j < 4; ++j) {
                int c = wn * 32 + j * 8 + g;
                float2 B = *(const float2*)(Wsm + c * WS_STRIDE + kc * 32 + k + 2 * tg);
                b[j][0] = __float_as_uint(B.x);
                b[j][1] = __float_as_uint(B.y);
            }
#pragma unroll
            for (int i = 0; i < 4; ++i)
#pragma unroll
                for (int j = 0; j < 4; ++j) MMA_TF32(acc[i][j], a[i], b[j]);
        }
        __syncthreads();
    }

    int rowsValid = NN - r0;
    if (rowsValid > 128) rowsValid = 128;

#pragma unroll
    for (int j = 0; j < 4; ++j) {
        int c0 = wn * 32 + j * 8 + 2 * tg;
        float b0 = g_bp[c0], b1 = g_bp[c0 + 1];
#pragma unroll
        for (int i = 0; i < 4; ++i) {
            acc[i][j][0] += b0; acc[i][j][1] += b1;
            acc[i][j][2] += b0; acc[i][j][3] += b1;
        }
    }

#pragma unroll
    for (int i = 0; i < 4; ++i) {
        int rlo = wm * 64 + i * 16 + g;
        int rhi = rlo + 8;
#pragma unroll
        for (int j = 0; j < 4; ++j) {
            int c0 = wn * 32 + j * 8 + 2 * tg;
            if (rlo < rowsValid) {
                __nv_bfloat162 p = __float22bfloat162_rn(
                    make_float2(acc[i][j][0], acc[i][j][1]));
                *(__nv_bfloat162*)(g_hb + (size_t)(r0 + rlo) * NF + c0) = p;
            }
            if (rhi < rowsValid) {
                __nv_bfloat162 p = __float22bfloat162_rn(
                    make_float2(acc[i][j][2], acc[i][j][3]));
                *(__nv_bfloat162*)(g_hb + (size_t)(r0 + rhi) * NF + c0) = p;
            }
        }
    }

    float aS[2][2][2], aD[2][2][2];
#pragma unroll
    for (int hl = 0; hl < 2; ++hl)
#pragma unroll
        for (int j2 = 0; j2 < 2; ++j2) {
            int base = (2 * wn + hl) * 16 + j2 * 8 + 2 * tg;
            aS[hl][j2][0] = attS[base];     aS[hl][j2][1] = attS[base + 1];
            aD[hl][j2][0] = attD[base];     aD[hl][j2][1] = attD[base + 1];
        }

#pragma unroll
    for (int i = 0; i < 4; ++i) {
#pragma unroll
        for (int hl = 0; hl < 2; ++hl) {
            float psl = 0.f, pdl = 0.f, psh = 0.f, pdh = 0.f;
#pragma unroll
            for (int j2 = 0; j2 < 2; ++j2) {
                int j = 2 * hl + j2;
                psl = fmaf(acc[i][j][0], aS[hl][j2][0],
                      fmaf(acc[i][j][1], aS[hl][j2][1], psl));
                pdl = fmaf(acc[i][j][0], aD[hl][j2][0],
                      fmaf(acc[i][j][1], aD[hl][j2][1], pdl));
                psh = fmaf(acc[i][j][2], aS[hl][j2][0],
                      fmaf(acc[i][j][3], aS[hl][j2][1], psh));
                pdh = fmaf(acc[i][j][2], aD[hl][j2][0],
                      fmaf(acc[i][j][3], aD[hl][j2][1], pdh));
            }
            psl += __shfl_xor_sync(0xffffffffu, psl, 1);
            psl += __shfl_xor_sync(0xffffffffu, psl, 2);
            pdl += __shfl_xor_sync(0xffffffffu, pdl, 1);
            pdl += __shfl_xor_sync(0xffffffffu, pdl, 2);
            psh += __shfl_xor_sync(0xffffffffu, psh, 1);
            psh += __shfl_xor_sync(0xffffffffu, psh, 2);
            pdh += __shfl_xor_sync(0xffffffffu, pdh, 1);
            pdh += __shfl_xor_sync(0xffffffffu, pdh, 2);
            if (tg == 0) {
                int h = 2 * wn + hl;
                int rlo = wm * 64 + i * 16 + g;
                int rhi = rlo + 8;
                if (rlo < rowsValid) {
                    int n = r0 + rlo;
                    g_asrc[n * NH + h] = psl;
                    g_adst[n * NH + h] = pdl;
                    float e = psl + pdl;
                    e = e > 0.f ? e : 0.2f * e;
                    g_s[n * NH + h] = __expf(e);
                }
                if (rhi < rowsValid) {
                    int n = r0 + rhi;
                    g_asrc[n * NH + h] = psh;
                    g_adst[n * NH + h] = pdh;
                    float e = psh + pdh;
                    e = e > 0.f ? e : 0.2f * e;
                    g_s[n * NH + h] = __expf(e);
                }
            }
        }
    }
}

// ---------------- K4: edge pass 1 — weights + denominators -----------------
__device__ __forceinline__ float lrelu_exp(float a, float b) {
    float e = a + b;
    e = e > 0.f ? e : 0.2f * e;
    return __expf(e);
}

__global__ void k_edge_s(const int* __restrict__ ei) {
    int e = blockIdx.x * blockDim.x + threadIdx.x;
    if (e >= NE) return;
    int s = ei[e];
    int d = ei[NE + e];
    float4 a0 = *(const float4*)(g_asrc + s * NH);
    float4 a1 = *(const float4*)(g_asrc + s * NH + 4);
    float4 b0 = *(const float4*)(g_adst + d * NH);
    float4 b1 = *(const float4*)(g_adst + d * NH + 4);
    float w0 = lrelu_exp(a0.x, b0.x), w1 = lrelu_exp(a0.y, b0.y);
    float w2 = lrelu_exp(a0.z, b0.z), w3 = lrelu_exp(a0.w, b0.w);
    float w4 = lrelu_exp(a1.x, b1.x), w5 = lrelu_exp(a1.y, b1.y);
    float w6 = lrelu_exp(a1.z, b1.z), w7 = lrelu_exp(a1.w, b1.w);
    __half2 hw[4];
    hw[0] = __floats2half2_rn(w0, w1);
    hw[1] = __floats2half2_rn(w2, w3);
    hw[2] = __floats2half2_rn(w4, w5);
    hw[3] = __floats2half2_rn(w6, w7);
    *(uint4*)(g_w + (size_t)e * NH) = *(uint4*)hw;
    float* sp = g_s + d * NH;
    red_v4(sp, w0, w1, w2, w3);
    red_v4(sp + 4, w4, w5, w6, w7);
}

// ---------------- K4b: g_s <- 0.125/s, wself <- selfw * 0.125/s ------------
__global__ void k_sinv() {
    int i = blockIdx.x * blockDim.x + threadIdx.x;
    if (i >= NN * NH) return;
    float si = 0.125f * __frcp_rn(g_s[i]);
    g_s[i] = si;
    float a = g_asrc[i] + g_adst[i];
    a = a > 0.f ? a : 0.2f * a;
    g_wself[i] = __expf(a) * si;
}

// ---------------- K5: edge pass 2 — message scatter (4 threads/edge) -------
// R14-best form: half2 w (coalesced) + sinv pair gather + 16 scalar h loads.
__global__ void k_edge_msg(const int* __restrict__ ei) {
    int gt = blockIdx.x * blockDim.x + threadIdx.x;
    int e = gt >> 2, q = gt & 3;
    if (e >= NE) return;
    int s = ei[e];
    int d = ei[NE + e];

    __half2 w2 = *(const __half2*)(g_w + (size_t)e * NH + q * 2);
    float2 wf = __half22float2(w2);
    float2 si2 = *(const float2*)(g_s + d * NH + q * 2);  // 0.125/s
    float2 alq;
    alq.x = wf.x * si2.x;
    alq.y = wf.y * si2.y;

    unsigned long long v0 = *(unsigned long long*)&alq;
    unsigned long long v1 = __shfl_xor_sync(0xffffffffu, v0, 1);
    unsigned long long v2 = __shfl_xor_sync(0xffffffffu, v0, 2);
    unsigned long long v3 = __shfl_xor_sync(0xffffffffu, v1, 2);
    float2 p1 = *(float2*)&v1, p2 = *(float2*)&v2, p3 = *(float2*)&v3;

    float al[8];
#pragma unroll
    for (int i = 0; i < 4; ++i) {
        int r = i ^ q;
        float2 p = (r == 0) ? alq : (r == 1) ? p1 : (r == 2) ? p2 : p3;
        al[2 * i] = p.x;
        al[2 * i + 1] = p.y;
    }

    const __nv_bfloat16* hrow = g_hb + (size_t)s * NF + q * 4;
    float r0 = 0.f, r1 = 0.f, r2 = 0.f, r3 = 0.f;
#pragma unroll
    for (int h = 0; h < NH; ++h) {
        __nv_bfloat162 p01 = *(const __nv_bfloat162*)(hrow + h * 16);
        __nv_bfloat162 p23 = *(const __nv_bfloat162*)(hrow + h * 16 + 2);
        float2 f01 = __bfloat1622float2(p01);
        float2 f23 = __bfloat1622float2(p23);
        r0 = fmaf(al[h], f01.x, r0);
        r1 = fmaf(al[h], f01.y, r1);
        r2 = fmaf(al[h], f23.x, r2);
        r3 = fmaf(al[h], f23.y, r3);
    }
    red_v4(g_acc + d * NC + q * 4, r0, r1, r2, r3);
}

// ---------------- K6: node finalize (precomputed self-loop weight) ---------
__global__ void k_node_final(const int* __restrict__ batch,
                             const float* __restrict__ bias) {
    int gt = blockIdx.x * blockDim.x + threadIdx.x;
    int n = gt >> 4, c = gt & 15;
    if (n >= NN) return;
    float v = g_acc[n * NC + c];
    const __nv_bfloat16* hr = g_hb + (size_t)n * NF;
    const float* ws = g_wself + n * NH;
#pragma unroll
    for (int h = 0; h < NH; ++h)
        v = fmaf(ws[h], __bfloat162float(hr[h * 16 + c]), v);
    v += bias[c];
    v = v > 0.f ? v : expm1f(v);
    int b = batch[n];
    atomicAdd(&g_pool[b * NC + c], v);
    if (c == 0) atomicAdd(&g_cnt[b], 1.0f);
}

// ---------------- K7: pooled mean ------------------------------------------
__global__ void k_pool_div(float* __restrict__ out) {
    int i = blockIdx.x * blockDim.x + threadIdx.x;
    if (i < NG * NC) {
        int g = i >> 4;
        out[i] = g_pool[i] / fmaxf(g_cnt[g], 1.0f);
    }
}

// ---------------- launch ----------------------------------------------------
extern "C" void kernel_launch(void* const* d_in, const int* in_sizes, int n_in,
                              void* d_out, int out_size) {
    const float* x = (const float*)d_in[0];
    const int* ei = (const int*)d_in[1];
    const int* batch = (const int*)d_in[2];
    const float* gamma = (const float*)d_in[3];
    const float* beta = (const float*)d_in[4];
    const float* W = (const float*)d_in[5];
    const float* attS = (const float*)d_in[6];
    const float* attD = (const float*)d_in[7];
    const float* bias = (const float*)d_in[8];
    float* out = (float*)d_out;

    cudaFuncSetAttribute(k_gemm, cudaFuncAttributeMaxDynamicSharedMemorySize,
                         GEMM_SMEM_BYTES);

    k_zero_stats<<<1, 128>>>();
    k_stats<<<512, 256>>>(x);
    k_prep<<<32, 256>>>(W, gamma, beta);
    k_gemm<<<(NN + 127) / 128, 256, GEMM_SMEM_BYTES>>>(x, attS, attD);
    k_edge_s<<<(NE + 255) / 256, 256>>>(ei);
    k_sinv<<<(NN * NH + 255) / 256, 256>>>();
    k_edge_msg<<<(NE * 4 + 255) / 256, 256>>>(ei);
    k_node_final<<<(NN * 16 + 255) / 256, 256>>>(batch, bias);
    k_pool_div<<<(NG * NC + 255) / 256, 256>>>(out);
}